// round 3
// baseline (speedup 1.0000x reference)
#include <cuda_runtime.h>
#include <cstdint>

#define Bc 1024
#define Sc 1024
#define Fc 36
#define Hc 20

typedef unsigned long long u64;

// ---------- packed f32x2 + fast-math helpers ----------
__device__ __forceinline__ u64 pk2(float lo, float hi) {
    u64 r; asm("mov.b64 %0, {%1, %2};" : "=l"(r) : "f"(lo), "f"(hi)); return r;
}
__device__ __forceinline__ void upk2(u64 v, float& lo, float& hi) {
    asm("mov.b64 {%0, %1}, %2;" : "=f"(lo), "=f"(hi) : "l"(v));
}
__device__ __forceinline__ u64 fma2(u64 a, u64 b, u64 c) {
    u64 d; asm("fma.rn.f32x2 %0, %1, %2, %3;" : "=l"(d) : "l"(a), "l"(b), "l"(c)); return d;
}
__device__ __forceinline__ u64 add2(u64 a, u64 b) {
    u64 d; asm("add.rn.f32x2 %0, %1, %2;" : "=l"(d) : "l"(a), "l"(b)); return d;
}
__device__ __forceinline__ float ex2a(float x) { float r; asm("ex2.approx.f32 %0, %1;" : "=f"(r) : "f"(x)); return r; }
__device__ __forceinline__ float rcpa(float x) { float r; asm("rcp.approx.f32 %0, %1;" : "=f"(r) : "f"(x)); return r; }
__device__ __forceinline__ float sigm(float x) { return rcpa(1.0f + ex2a(-1.4426950408889634f * x)); }
__device__ __forceinline__ float tanh_(float x) {
    return fmaf(2.0f, rcpa(1.0f + ex2a(-2.8853900817779268f * x)), -1.0f);
}

// ---------- dtype detection: int64 vs int32 onehots ----------
__device__ int g_is64;

__global__ void detect_kernel(const int* __restrict__ oh32) {
    int t = threadIdx.x;                    // 128 threads, check odd 32-bit words
    int v = oh32[2 * t + 1];
    unsigned m = __ballot_sync(0xFFFFFFFFu, v != 0);
    __shared__ int any[4];
    if ((t & 31) == 0) any[t >> 5] = (m != 0);
    __syncthreads();
    if (t == 0) g_is64 = !(any[0] | any[1] | any[2] | any[3]);
}

// ---------- kernel 1: embedding concat -> origin ----------
__global__ void embed_kernel(const float* __restrict__ x, const void* __restrict__ ohraw,
                             const float* __restrict__ e0, const float* __restrict__ e1,
                             const float* __restrict__ e2, const float* __restrict__ e3,
                             float* __restrict__ org)
{
    int idx = blockIdx.x * blockDim.x + threadIdx.x;
    if (idx >= Bc * Sc) return;
    const float4* xr = reinterpret_cast<const float4*>(x + (size_t)idx * 12);
    float4 v0 = xr[0], v1 = xr[1], v2 = xr[2];

    long long i0, i1, i2, i3;
    if (g_is64) {
        const longlong2* op = reinterpret_cast<const longlong2*>((const long long*)ohraw + (size_t)idx * 4);
        longlong2 a = op[0], b = op[1];
        i0 = a.x; i1 = a.y; i2 = b.x; i3 = b.y;
    } else {
        int4 a = *reinterpret_cast<const int4*>((const int*)ohraw + (size_t)idx * 4);
        i0 = a.x; i1 = a.y; i2 = a.z; i3 = a.w;
    }
    i0 = i0 < 0 ? 0 : (i0 > 9  ? 9  : i0);
    i1 = i1 < 0 ? 0 : (i1 > 19 ? 19 : i1);
    i2 = i2 < 0 ? 0 : (i2 > 49 ? 49 : i2);
    i3 = i3 < 0 ? 0 : (i3 > 99 ? 99 : i3);

    float4* out = reinterpret_cast<float4*>(org + (size_t)idx * 36);
    out[0] = v0; out[1] = v1; out[2] = v2;
    out[3] = *reinterpret_cast<const float4*>(e0 + i0 * 4);
    out[4] = *reinterpret_cast<const float4*>(e1 + i1 * 4);
    const float4* p2 = reinterpret_cast<const float4*>(e2 + i2 * 8);
    out[5] = p2[0]; out[6] = p2[1];
    const float4* p3 = reinterpret_cast<const float4*>(e3 + i3 * 8);
    out[7] = p3[0]; out[8] = p3[1];
}

// ---------- packed dots (weights in regs, x/h broadcast from shared) ----------
__device__ __forceinline__ u64 dot36(const u64* __restrict__ xsh, const u64* w, u64 acc0) {
    const ulonglong2* xp = reinterpret_cast<const ulonglong2*>(xsh);
    u64 a0 = acc0, a1 = 0ULL, a2 = 0ULL, a3 = 0ULL;
#pragma unroll
    for (int k = 0; k < 18; k++) {
        ulonglong2 v = xp[k];
        if ((k & 1) == 0) { a0 = fma2(v.x, w[2*k], a0); a1 = fma2(v.y, w[2*k+1], a1); }
        else              { a2 = fma2(v.x, w[2*k], a2); a3 = fma2(v.y, w[2*k+1], a3); }
    }
    return add2(add2(a0, a2), add2(a1, a3));
}
__device__ __forceinline__ u64 dot20(const u64* __restrict__ hsh, const u64* w, u64 acc0) {
    const ulonglong2* hp = reinterpret_cast<const ulonglong2*>(hsh);
    u64 a0 = acc0, a1 = 0ULL, a2 = 0ULL, a3 = 0ULL;
#pragma unroll
    for (int k = 0; k < 10; k++) {
        ulonglong2 v = hp[k];
        if ((k & 1) == 0) { a0 = fma2(v.x, w[2*k], a0); a1 = fma2(v.y, w[2*k+1], a1); }
        else              { a2 = fma2(v.x, w[2*k], a2); a3 = fma2(v.y, w[2*k+1], a3); }
    }
    return add2(add2(a0, a2), add2(a1, a3));
}

// ---------- kernel 2: persistent GRU, 64 threads = 2 warps per block ----------
// Lane l (<60) owns full gate row l: 56 dup-packed weights = 112 regs.
// h-update on lanes 40..59; FC (smem dup weights) on lanes 0..35; prefetch 0..17.
__global__ void __launch_bounds__(64) gru_kernel(
    const float* __restrict__ org,
    const float* __restrict__ Wih1, const float* __restrict__ Whh1,
    const float* __restrict__ bih1, const float* __restrict__ bhh1,
    const float* __restrict__ Wih2, const float* __restrict__ Whh2,
    const float* __restrict__ bih2, const float* __restrict__ bhh2,
    const float* __restrict__ Wfc,  const float* __restrict__ bfc,
    float* __restrict__ xs)
{
    const int l = threadIdx.x;
    const int b0 = blockIdx.x * 2;
    const size_t base0 = (size_t)b0 * Sc * Fc;
    const size_t base1 = base0 + (size_t)Sc * Fc;

    __shared__ __align__(16) u64 xring[4][Fc];   // encoder input ring (packed pair)
    __shared__ __align__(16) u64 hbuf[Hc];
    __shared__ __align__(16) u64 g[40];          // r,z gates: gi+gh combined
    __shared__ __align__(16) u64 gan[Hc];        // n gate: gi part
    __shared__ __align__(16) u64 gbn[Hc];        // n gate: gh part
    __shared__ __align__(16) u64 xdec[Fc];
    __shared__ u64 wfc_sh[Fc][21];               // pad 21 -> 2-way conflict max
    __shared__ u64 bfc_sh[Fc];

    const bool gate = (l < 60);
    const bool hl   = (l >= 40 && l < 60);
    const int  hj   = l - 40;
    const bool fcl  = (l < Fc);
    const bool pfl  = (l < 18);

    u64 wx[Fc], wh[Hc];
    u64 ba = 0ULL, bb = 0ULL;

    // FC weights -> shared (dup-packed)
    for (int idx = l; idx < Fc * Hc; idx += 64) {
        int r = idx / Hc, k = idx % Hc;
        float w = Wfc[r * Hc + k];
        wfc_sh[r][k] = pk2(w, w);
    }
    if (fcl) { float t = bfc[l]; bfc_sh[l] = pk2(t, t); }

    // encoder gate weights -> regs
    if (gate) {
#pragma unroll
        for (int f = 0; f < Fc; f++) { float w = Wih1[l * Fc + f]; wx[f] = pk2(w, w); }
#pragma unroll
        for (int k = 0; k < Hc; k++) { float w = Whh1[l * Hc + k]; wh[k] = pk2(w, w); }
        float t1 = bih1[l]; ba = pk2(t1, t1);
        float t2 = bhh1[l]; bb = pk2(t2, t2);
    }
    if (hl) hbuf[hj] = 0ULL;

    // prefetch: lanes 0..17 own feature pair (2l, 2l+1); 2 register generations
    float2 qA0 = {0.f,0.f}, qA1 = {0.f,0.f}, qB0 = {0.f,0.f}, qB1 = {0.f,0.f};
    if (pfl) {
#pragma unroll
        for (int s = 0; s < 3; s++) {
            float2 a = *reinterpret_cast<const float2*>(org + base0 + s * Fc + 2 * l);
            float2 b = *reinterpret_cast<const float2*>(org + base1 + s * Fc + 2 * l);
            xring[s][2*l]   = pk2(a.x, b.x);
            xring[s][2*l+1] = pk2(a.y, b.y);
        }
        qA0 = *reinterpret_cast<const float2*>(org + base0 + 3 * Fc + 2 * l);
        qA1 = *reinterpret_cast<const float2*>(org + base1 + 3 * Fc + 2 * l);
        qB0 = *reinterpret_cast<const float2*>(org + base0 + 4 * Fc + 2 * l);
        qB1 = *reinterpret_cast<const float2*>(org + base1 + 4 * Fc + 2 * l);
    }
    __syncthreads();

    // ================= encoder: S steps, 2 barriers/step =================
    for (int t = 0; t < Sc; t++) {
        float2 n0 = {0.f,0.f}, n1 = {0.f,0.f};
        if (pfl && (t + 5 < Sc)) {        // issue LDG for t+5 (2 steps of slack)
            n0 = *reinterpret_cast<const float2*>(org + base0 + (size_t)(t + 5) * Fc + 2 * l);
            n1 = *reinterpret_cast<const float2*>(org + base1 + (size_t)(t + 5) * Fc + 2 * l);
        }
        if (gate) {
            u64 aa  = dot36(xring[t & 3], wx, ba);
            u64 bbv = dot20(hbuf, wh, bb);
            if (l < 40) g[l] = add2(aa, bbv);
            else { gan[l - 40] = aa; gbn[l - 40] = bbv; }
        }
        if (pfl && (t + 3 < Sc)) {        // STS generation loaded 2 steps ago
            int s = (t + 3) & 3;
            xring[s][2*l]   = pk2(qA0.x, qA1.x);
            xring[s][2*l+1] = pk2(qA0.y, qA1.y);
        }
        qA0 = qB0; qA1 = qB1; qB0 = n0; qB1 = n1;
        __syncthreads();
        if (hl) {
            float rx, ry, zx, zy, ax, ay, bx, by, hx, hy;
            upk2(g[hj], rx, ry); upk2(g[hj + 20], zx, zy);
            upk2(gan[hj], ax, ay); upk2(gbn[hj], bx, by);
            upk2(hbuf[hj], hx, hy);
            float r0 = sigm(rx), r1 = sigm(ry);
            float z0 = sigm(zx), z1 = sigm(zy);
            float nn0 = tanh_(fmaf(r0, bx, ax));
            float nn1 = tanh_(fmaf(r1, by, ay));
            hbuf[hj] = pk2(fmaf(z0, hx - nn0, nn0), fmaf(z1, hy - nn1, nn1));
        }
        __syncthreads();
    }

    // ================= phase switch =================
    if (gate) {
#pragma unroll
        for (int f = 0; f < Fc; f++) { float w = Wih2[l * Fc + f]; wx[f] = pk2(w, w); }
#pragma unroll
        for (int k = 0; k < Hc; k++) { float w = Whh2[l * Hc + k]; wh[k] = pk2(w, w); }
        float t1 = bih2[l]; ba = pk2(t1, t1);
        float t2 = bhh2[l]; bb = pk2(t2, t2);
    }
    if (hl) {
        float hx, hy; upk2(hbuf[hj], hx, hy);
        hbuf[hj] = pk2(tanh_(hx), tanh_(hy));
    }
    __syncthreads();

    // x0 = tanh(h @ Wfc.T + bfc) -> xs[:, S-1, :]
    if (fcl) {
        u64 acc = bfc_sh[l];
        const ulonglong2* hp = reinterpret_cast<const ulonglong2*>(hbuf);
#pragma unroll
        for (int k = 0; k < 10; k++) {
            ulonglong2 v = hp[k];
            acc = fma2(v.x, wfc_sh[l][2*k], acc);
            acc = fma2(v.y, wfc_sh[l][2*k+1], acc);
        }
        float xx, xy; upk2(acc, xx, xy);
        xx = tanh_(xx); xy = tanh_(xy);
        xdec[l] = pk2(xx, xy);
        xs[base0 + (size_t)(Sc - 1) * Fc + l] = xx;
        xs[base1 + (size_t)(Sc - 1) * Fc + l] = xy;
    }
    __syncthreads();

    // ================= decoder: S-1 steps, 3 barriers/step =================
    for (int k = 1; k < Sc; k++) {
        if (gate) {
            u64 aa  = dot36(xdec, wx, ba);
            u64 bbv = dot20(hbuf, wh, bb);
            if (l < 40) g[l] = add2(aa, bbv);
            else { gan[l - 40] = aa; gbn[l - 40] = bbv; }
        }
        __syncthreads();
        if (hl) {
            float rx, ry, zx, zy, ax, ay, bx, by, hx, hy;
            upk2(g[hj], rx, ry); upk2(g[hj + 20], zx, zy);
            upk2(gan[hj], ax, ay); upk2(gbn[hj], bx, by);
            upk2(hbuf[hj], hx, hy);
            float r0 = sigm(rx), r1 = sigm(ry);
            float z0 = sigm(zx), z1 = sigm(zy);
            float nn0 = tanh_(fmaf(r0, bx, ax));
            float nn1 = tanh_(fmaf(r1, by, ay));
            float g0 = fmaf(z0, hx - nn0, nn0);
            float g1 = fmaf(z1, hy - nn1, nn1);
            hbuf[hj] = pk2(tanh_(g0), tanh_(g1));     // decoder outer tanh
        }
        __syncthreads();
        if (fcl) {
            u64 acc = bfc_sh[l];
            const ulonglong2* hp = reinterpret_cast<const ulonglong2*>(hbuf);
#pragma unroll
            for (int kk = 0; kk < 10; kk++) {
                ulonglong2 v = hp[kk];
                acc = fma2(v.x, wfc_sh[l][2*kk], acc);
                acc = fma2(v.y, wfc_sh[l][2*kk+1], acc);
            }
            float xx, xy; upk2(acc, xx, xy);
            xx = tanh_(xx); xy = tanh_(xy);
            xdec[l] = pk2(xx, xy);
            const size_t row = (size_t)(Sc - 1 - k) * Fc;
            xs[base0 + row + l] = xx;
            xs[base1 + row + l] = xy;
        }
        __syncthreads();
    }
}

// ---------- launcher ----------
extern "C" void kernel_launch(void* const* d_in, const int* in_sizes, int n_in,
                              void* d_out, int out_size)
{
    const float* x    = (const float*)d_in[0];
    const void*  oh   = d_in[1];
    const float* e0   = (const float*)d_in[2];
    const float* e1   = (const float*)d_in[3];
    const float* e2   = (const float*)d_in[4];
    const float* e3   = (const float*)d_in[5];
    const float* Wih1 = (const float*)d_in[6];
    const float* Whh1 = (const float*)d_in[7];
    const float* bih1 = (const float*)d_in[8];
    const float* bhh1 = (const float*)d_in[9];
    const float* Wih2 = (const float*)d_in[10];
    const float* Whh2 = (const float*)d_in[11];
    const float* bih2 = (const float*)d_in[12];
    const float* bhh2 = (const float*)d_in[13];
    const float* Wfc  = (const float*)d_in[14];
    const float* bfc  = (const float*)d_in[15];

    float* out = (float*)d_out;
    float* org = out;                              // output #1 (origin), also GRU input
    float* xs  = out + (size_t)Bc * Sc * Fc;       // output #2 (decoded, time-flipped)

    detect_kernel<<<1, 128>>>((const int*)oh);
    embed_kernel<<<(Bc * Sc + 127) / 128, 128>>>(x, oh, e0, e1, e2, e3, org);
    gru_kernel<<<Bc / 2, 64>>>(org, Wih1, Whh1, bih1, bhh1,
                               Wih2, Whh2, bih2, bhh2, Wfc, bfc, xs);
}